// round 16
// baseline (speedup 1.0000x reference)
#include <cuda_runtime.h>

// NutritionLoss: Gaussian soft-lookup over NF=1000 foods is numerically a
// one-hot for integer ids (off-weight exp(-100) ~ 3.7e-44) -> hard gather.
//
//   loss = 5 * mean_b sum_c | sum_{d,m,s} (data[pid,c]*pamt - data[tid,c]*tamt) / 700 |
//
// R13 -> R16: R13's warp-per-batch structure (no smem / no syncthreads /
// REDUX / packed single-atomic tail) was right, but 1 warp per SM (occ=1.5%)
// serialized the two dependent memory stages (input LDG -> gather LDG) on
// the wall clock. Repack: 8 warps per block, 8 blocks -> 8 co-resident
// warps per SM hide each other's stalls, and the 20KB table (157 lines)
// goes L1-hot across the block's ~1120 gathers.

#define NF 1000
#define NC 5
#define ELEMS 448          // D*M*S = 7*4*16
#define BATCH 64
#define SLOTS_PER_LANE 14  // 448 / 32
#define WARPS_PER_BLOCK 8
#define NBLOCKS (BATCH / WARPS_PER_BLOCK)   // 8

#define FP_SCALE 512.0f    // 2^9: 32 lanes * 14 slots * 5000 * 512 = 1.15e9 < 2^31
#define CNT_ONE  (1ULL << 56)
#define SUM_MASK (CNT_ONE - 1ULL)

__device__ unsigned long long d_acc = 0ULL;  // [63:56]=arrivals, [55:0]=fixed-point sum

__global__ __launch_bounds__(WARPS_PER_BLOCK * 32) void nl_main(
    const float* __restrict__ y_pred,   // [B,D,M,S,2] interleaved (id, amt)
    const float* __restrict__ y,        // [B,D,M,S,2]
    const float* __restrict__ data,     // [NF,NC]
    float* __restrict__ out)            // scalar
{
    const int lane = threadIdx.x & 31;
    const int b = blockIdx.x * WARPS_PER_BLOCK + (threadIdx.x >> 5);  // warp = batch

    const float2* __restrict__ ypv = reinterpret_cast<const float2*>(y_pred) + b * ELEMS;
    const float2* __restrict__ ytv = reinterpret_cast<const float2*>(y)      + b * ELEMS;

    // Preload all 28 input pairs (coalesced, all LDGs in flight together).
    float2 p[SLOTS_PER_LANE], q[SLOTS_PER_LANE];
    #pragma unroll
    for (int i = 0; i < SLOTS_PER_LANE; i++) {
        p[i] = ypv[i * 32 + lane];
        q[i] = ytv[i * 32 + lane];
    }

    // Gather + accumulate: 140 table loads per thread-group, all independent;
    // table is 157 cache lines -> L1-hot after block warmup.
    float facc[NC] = {0.f, 0.f, 0.f, 0.f, 0.f};
    #pragma unroll
    for (int i = 0; i < SLOTS_PER_LANE; i++) {
        const int pid = __float2int_rn(p[i].x);   // matches jnp.round (no .5 cases)
        const int tid = __float2int_rn(q[i].x);   // true ids are exact integers
        const float pamt = p[i].y;
        const float tamt = q[i].y;
        #pragma unroll
        for (int c = 0; c < NC; c++)
            facc[c] = fmaf(__ldg(&data[pid * NC + c]), pamt,
                      fmaf(-__ldg(&data[tid * NC + c]), tamt, facc[c]));
    }

    // Fixed-point REDUX across the warp: one instruction per category,
    // bitwise-deterministic.
    const unsigned full = 0xffffffffu;
    unsigned long long tot = 0ULL;
    #pragma unroll
    for (int c = 0; c < NC; c++) {
        int s = __reduce_add_sync(full, __float2int_rn(facc[c] * FP_SCALE));
        tot += (unsigned long long)(s < 0 ? -s : s);   // |per-batch category sum|
    }

    // Packed single-atomic tail: data + arrival counter in one word, no fences.
    if (lane == 0) {
        unsigned long long payload = tot | CNT_ONE;
        unsigned long long prev = atomicAdd(&d_acc, payload);
        if ((prev >> 56) == (BATCH - 1)) {
            unsigned long long total_fx = (prev + payload) & SUM_MASK;
            atomicExch(&d_acc, 0ULL);     // self-reset for next graph replay
            // * 1/FP_SCALE, * (1/700) elementwise, * (1/B) mean, * 5 penalty
            out[0] = (float)total_fx * (5.0f / (FP_SCALE * 700.0f * (float)BATCH));
        }
    }
}

extern "C" void kernel_launch(void* const* d_in, const int* in_sizes, int n_in,
                              void* d_out, int out_size) {
    const float* y_pred = (const float*)d_in[0];
    const float* y      = (const float*)d_in[1];
    const float* data   = (const float*)d_in[2];
    float* out = (float*)d_out;

    nl_main<<<NBLOCKS, WARPS_PER_BLOCK * 32>>>(y_pred, y, data, out);
}

// round 17
// speedup vs baseline: 1.9183x; 1.9183x over previous
#include <cuda_runtime.h>

// NutritionLoss: Gaussian soft-lookup over NF=1000 foods is numerically a
// one-hot for integer ids (off-weight exp(-100) ~ 3.7e-44) -> hard gather.
//
//   loss = 5 * mean_b sum_c | sum_{d,m,s} (data[pid,c]*pamt - data[tid,c]*tamt) / 700 |
//
// R16 -> R17: back to the proven 64x448 chassis (R12, best kernel 6.2us).
// Two changes:
//  1. ZERO contended atomics. 64 CTAs hammering one atomic word serialize
//     at ~n_conc*32*0.854 ~ 1700+ cyc (B300 L2-atom law). Replace with a
//     flag-in-word scoreboard: each block does ONE plain 32-bit store
//     (bit31=valid | bits[30:0]=fixed-point |batch sum|) to its own
//     128B-strided slot. Block 63 polls the 64 slots (all blocks are
//     co-resident: 64 << 148 SMs, no deadlock), folds, writes out, and
//     resets slots for the next graph replay.
//  2. Reductions via fixed-point REDUX (1 instr/category) at both warp and
//     cross-warp level; bitwise-deterministic.

#define NF 1000
#define NC 5
#define ELEMS 448          // D*M*S = 7*4*16
#define BATCH 64
#define NWARPS 14          // 448 / 32

#define FP_SCALE 128.0f    // 2^7: worst case 448*5000*128*5 = 1.43e9 < 2^31
#define FLAG     0x80000000u
#define VMASK    0x7FFFFFFFu
#define PSTRIDE  32        // 32 uints = 128B between slots (distinct L2 lines)

__device__ volatile unsigned d_part[BATCH * PSTRIDE];   // zero-initialized

__global__ __launch_bounds__(ELEMS) void nl_main(
    const float* __restrict__ y_pred,   // [B,D,M,S,2] interleaved (id, amt)
    const float* __restrict__ y,        // [B,D,M,S,2]
    const float* __restrict__ data,     // [NF,NC]
    float* __restrict__ out)            // scalar
{
    __shared__ int swarp[NWARPS][NC];

    const int t = threadIdx.x;
    const int b = blockIdx.x;

    // One (d,m,s) slot per thread; (id, amt) pairs interleaved -> float2.
    const float2 yp = reinterpret_cast<const float2*>(y_pred)[b * ELEMS + t];
    const float2 yt = reinterpret_cast<const float2*>(y)[b * ELEMS + t];

    const int pid = __float2int_rn(yp.x);   // matches jnp.round (no .5 cases)
    const int tid = __float2int_rn(yt.x);   // true ids are exact integers
    const float pamt = yp.y;
    const float tamt = yt.y;

    // Direct gather from the 20KB table (L2/L1-hot); 10 independent LDGs.
    float facc[NC];
    #pragma unroll
    for (int c = 0; c < NC; c++)
        facc[c] = __ldg(&data[pid * NC + c]) * pamt
                - __ldg(&data[tid * NC + c]) * tamt;

    // Warp-level fixed-point REDUX: one instruction per category.
    const unsigned full = 0xffffffffu;   // 448 = 14 full warps
    #pragma unroll
    for (int c = 0; c < NC; c++) {
        int s = __reduce_add_sync(full, __float2int_rn(facc[c] * FP_SCALE));
        if ((t & 31) == 0) swarp[t >> 5][c] = s;
    }
    __syncthreads();

    // Cross-warp: warp-0 lanes 0..13 REDUX the 14 warp partials per category.
    if (t < NWARPS) {
        const unsigned m14 = 0x3FFFu;
        unsigned tot = 0;
        #pragma unroll
        for (int c = 0; c < NC; c++) {
            int s = __reduce_add_sync(m14, swarp[t][c]);
            tot += (unsigned)(s < 0 ? -s : s);   // |per-batch category sum|
        }
        // ONE plain store: valid flag + data in the same 32-bit word.
        if (t == 0) d_part[b * PSTRIDE] = FLAG | tot;
    }

    // Block 63: scoreboard wait + final fold + replay reset.
    if (b == BATCH - 1 && t < 32) {
        unsigned v0, v1;
        do {
            v0 = d_part[t * PSTRIDE];          // volatile -> L2 every poll
            v1 = d_part[(t + 32) * PSTRIDE];
        } while (__ballot_sync(full, (v0 & v1) >> 31) != full);

        // 64-bit lane sums (32-bit could overflow worst-case), shuffle-fold.
        unsigned long long s = (unsigned long long)(v0 & VMASK)
                             + (unsigned long long)(v1 & VMASK);
        #pragma unroll
        for (int o = 16; o > 0; o >>= 1) s += __shfl_down_sync(full, s, o);

        if (t == 0)
            // * 1/FP_SCALE, * (1/700) elementwise, * (1/B) mean, * 5 penalty
            out[0] = (float)s * (5.0f / (FP_SCALE * 700.0f * (float)BATCH));

        // Reset scoreboard for the next graph replay (kernel-boundary
        // ordering makes these visible before any next-replay store).
        d_part[t * PSTRIDE] = 0u;
        d_part[(t + 32) * PSTRIDE] = 0u;
    }
}

extern "C" void kernel_launch(void* const* d_in, const int* in_sizes, int n_in,
                              void* d_out, int out_size) {
    const float* y_pred = (const float*)d_in[0];
    const float* y      = (const float*)d_in[1];
    const float* data   = (const float*)d_in[2];
    float* out = (float*)d_out;

    nl_main<<<BATCH, ELEMS>>>(y_pred, y, data, out);
}